// round 12
// baseline (speedup 1.0000x reference)
#include <cuda_runtime.h>
#include <math.h>

// ---------------------------------------------------------------------------
// GatingNeuralAdaptiveBias — terminal form: out(x0, sigma) is a scalar 2D
// function -> tabulate the OUTPUT itself (513 x 2049 fp32, 4.2MB, L2) and the
// main kernel is one bilinear lookup per pixel.
//   K1: per-node e rows (fp32) + [s,q,d] sidecars + coarse gate g rows + consts
//   K2: coarse w0(x0,sigma) table 129x257 (sigmoid applied)
//   K3: out2d build -- X = E0 @ E1^T cross-GEMM + closed-form LN epilogue
//   K4: main -- x0, sigma, bilinear(out2d)
// ---------------------------------------------------------------------------

typedef unsigned int uint;

#define PI_F 3.14159265358979323846f
#define NE0 512
#define NE1 2048
#define NG0 128
#define NG1 256
#define OST 2049              // out2d row stride (NE1+1)

__device__ __align__(16) float g_e0f[516 * 64];
__device__ __align__(16) float g_e1f[2052 * 64];
__device__ __align__(16) float g_s0[516], g_q0[516], g_d0[516];
__device__ __align__(16) float g_s1[2052], g_q1[2052], g_d1[2052];
__device__ __align__(16) float g_g0c[132 * 64];
__device__ __align__(16) float g_g1c[260 * 64];
__device__ __align__(16) float g_w2d[129 * 257 + 8];
__device__ __align__(16) float g_out2d[513 * OST + 8];
// g_pre: [0..63] wd ; 64 itemp ; 65 sbw ; 66 bg2d ; 67 c1s
__device__ __align__(16) float g_pre[68];

__device__ __forceinline__ float silu_acc(float v) { return v / (1.0f + expf(-v)); }

// theta at a sigma node (build side); sigma in [0,4]; node 0 -> -pi.
__device__ __forceinline__ float theta_from_sigma(float sigma, int ent) {
    if (ent == 0) return -PI_F;
    const float tau = (sigma >= 2.0f) ? sigma - 2.0f : sigma + 2.0f;
    float x, y;
    if      (tau < 1.0f) { x = 1.0f - tau; y = tau; }
    else if (tau < 2.0f) { x = 1.0f - tau; y = 2.0f - tau; }
    else if (tau < 3.0f) { x = tau - 3.0f; y = 2.0f - tau; }
    else                 { x = tau - 3.0f; y = tau - 4.0f; }
    return atan2f(y, x);
}

// ==================== K1: node rows + sidecars + consts ====================
#define NB_E0 513
#define NB_E1 2049
#define NB_G0 129
#define NB_G1 257
#define NB_TOT (NB_E0 + NB_E1 + NB_G0 + NB_G1)   // 2948; grid = 2949
__global__ void __launch_bounds__(64)
k_nodes(const float* __restrict__ lsc,
        const float* __restrict__ W1,  const float* __restrict__ b1,
        const float* __restrict__ W2,  const float* __restrict__ b2,
        const float* __restrict__ fg,  const float* __restrict__ fb,
        const float* __restrict__ Wg1, const float* __restrict__ bg1,
        const float* __restrict__ Wg2, const float* __restrict__ bg2,
        const float* __restrict__ temp,
        const float* __restrict__ lng, const float* __restrict__ lnb,
        const float* __restrict__ Wo,  const float* __restrict__ bo)
{
    const int blk = blockIdx.x;
    const int tid = threadIdx.x;

    if (blk == NB_TOT) {                  // constants
        g_pre[tid] = Wg2[2 * tid] - Wg2[2 * tid + 1];
        if (tid == 0) {
            float s = bo[0], cs = 0.0f;
            for (int k = 0; k < 64; k++) { s += lnb[k] * Wo[k]; cs += lng[k] * Wo[k]; }
            g_pre[64] = expf(-temp[0]);
            g_pre[65] = s;
            g_pre[66] = bg2[0] - bg2[1];
            g_pre[67] = cs;
        }
        return;
    }

    __shared__ float sh[64];
    __shared__ float sred[6];

    int mode, ch, ent;
    if      (blk < NB_E0)                 { mode = 0; ch = 0; ent = blk; }
    else if (blk < NB_E0 + NB_E1)         { mode = 0; ch = 1; ent = blk - NB_E0; }
    else if (blk < NB_E0 + NB_E1 + NB_G0) { mode = 1; ch = 0; ent = blk - NB_E0 - NB_E1; }
    else                                  { mode = 1; ch = 1; ent = blk - NB_E0 - NB_E1 - NB_G0; }

    float x;
    if (ch == 0) x = (float)ent * (mode ? (1.0f / NG0) : (1.0f / NE0));
    else {
        const float sig = (float)ent * (mode ? (4.0f / NG1) : (4.0f / NE1));
        x = theta_from_sigma(sig, ent);
    }
    const float sc = expf(lsc[ch]);

    float ft[9];
    ft[0] = x * sc;
    #pragma unroll
    for (int q = 0; q < 4; q++) {
        float s, c;
        sincosf(x * (float)(1 << q), &s, &c);
        ft[1 + 2 * q] = s * sc;
        ft[2 + 2 * q] = c * sc;
    }

    float z = b1[tid];
    #pragma unroll
    for (int f = 0; f < 9; f++) z = fmaf(ft[f], W1[f * 64 + tid], z);
    sh[tid] = silu_acc(z);
    __syncthreads();

    float e = 0.0f;
    #pragma unroll 8
    for (int j = 0; j < 64; j++) e = fmaf(sh[j], W2[j * 64 + tid], e);
    e = fmaf(e + b2[tid], fg[ch * 64 + tid], fb[ch * 64 + tid]);

    if (mode == 0) {
        float* ef = ch ? g_e1f : g_e0f;
        ef[ent * 64 + tid] = e;
        const float c1d = lng[tid] * Wo[tid];
        float s = e, q = e * e, d = e * c1d;
        #pragma unroll
        for (int o = 16; o > 0; o >>= 1) {
            s += __shfl_xor_sync(0xFFFFFFFFu, s, o);
            q += __shfl_xor_sync(0xFFFFFFFFu, q, o);
            d += __shfl_xor_sync(0xFFFFFFFFu, d, o);
        }
        if ((tid & 31) == 0) {
            const int w = tid >> 5;
            sred[w * 3 + 0] = s;  sred[w * 3 + 1] = q;  sred[w * 3 + 2] = d;
        }
        __syncthreads();
        if (tid == 0) {
            if (ch) { g_s1[ent] = sred[0] + sred[3]; g_q1[ent] = sred[1] + sred[4]; g_d1[ent] = sred[2] + sred[5]; }
            else    { g_s0[ent] = sred[0] + sred[3]; g_q0[ent] = sred[1] + sred[4]; g_d0[ent] = sred[2] + sred[5]; }
        }
    } else {
        __syncthreads();
        sh[tid] = e;
        __syncthreads();
        float g = (ch == 0) ? bg1[tid] : 0.0f;
        #pragma unroll 8
        for (int k = 0; k < 64; k++)
            g = fmaf(sh[k], Wg1[(ch * 64 + k) * 64 + tid], g);
        (ch ? g_g1c : g_g0c)[ent * 64 + tid] = g;
    }
}

// ==================== K2: coarse w0 table ==================================
__global__ void __launch_bounds__(256)
k_w2d()
{
    __shared__ float s_wd[64];
    const int tid = threadIdx.x;
    if (tid < 64) s_wd[tid] = g_pre[tid];
    __syncthreads();

    const int idx = blockIdx.x * 256 + tid;
    if (idx >= 129 * 257) return;
    const int i0 = idx / 257;
    const int i1 = idx - i0 * 257;

    const float4* a = reinterpret_cast<const float4*>(&g_g0c[i0 * 64]);
    const float4* b = reinterpret_cast<const float4*>(&g_g1c[i1 * 64]);
    float acc = g_pre[66];
    #pragma unroll 4
    for (int k = 0; k < 16; k++) {
        const float4 av = __ldg(&a[k]);
        const float4 bv = __ldg(&b[k]);
        acc = fmaf(silu_acc(av.x + bv.x), s_wd[4 * k],     acc);
        acc = fmaf(silu_acc(av.y + bv.y), s_wd[4 * k + 1], acc);
        acc = fmaf(silu_acc(av.z + bv.z), s_wd[4 * k + 2], acc);
        acc = fmaf(silu_acc(av.w + bv.w), s_wd[4 * k + 3], acc);
    }
    g_w2d[idx] = 1.0f / (1.0f + expf(-acc * g_pre[64]));
}

// ==================== K3: out2d build (cross-GEMM + epilogue) ==============
// grid = 129 i0-groups (4 rows each) x 5 i1-segments (512 cols each)
__global__ void __launch_bounds__(256)
k_out2d()
{
    __shared__ __align__(16) float se0[4 * 64];
    __shared__ float sw0[2 * 264];
    __shared__ float sS[12];   // s0,q0,d0 for 4 rows

    const int blk   = blockIdx.x;
    const int i0seg = blk / 5;
    const int i1seg = blk - i0seg * 5;
    const int tid   = threadIdx.x;

    {   // stage e0 rows (zero-fill invalid rows)
        const int r = tid >> 6, k = tid & 63;
        const int i0 = i0seg * 4 + r;
        se0[tid] = (i0 <= NE0) ? g_e0f[i0 * 64 + k] : 0.0f;
    }
    {   // stage 2 coarse-w0 rows
        const int ra = i0seg;
        const int rb = (i0seg + 1 <= 128) ? i0seg + 1 : 128;
        for (int t = tid; t < 257; t += 256) {
            sw0[t]       = g_w2d[ra * 257 + t];
            sw0[264 + t] = g_w2d[rb * 257 + t];
        }
        if (tid < 7) { sw0[257 + tid] = 0.0f; sw0[264 + 257 + tid] = 0.0f; }
    }
    if (tid < 4) {
        const int i0 = i0seg * 4 + tid;
        const int ic = (i0 <= NE0) ? i0 : NE0;
        sS[tid]     = g_s0[ic];
        sS[4 + tid] = g_q0[ic];
        sS[8 + tid] = g_d0[ic];
    }
    __syncthreads();

    const int i1 = i1seg * 512 + tid * 2;
    if (i1 > NE1) return;

    // cross inner products X[r][c] = e0_r . e1_{i1+c}
    float X[8] = {0, 0, 0, 0, 0, 0, 0, 0};
    #pragma unroll 4
    for (int kc = 0; kc < 16; kc++) {
        const float4 a = *reinterpret_cast<const float4*>(&g_e1f[i1 * 64 + kc * 4]);
        const float4 b = *reinterpret_cast<const float4*>(&g_e1f[(i1 + 1) * 64 + kc * 4]);
        #pragma unroll
        for (int r = 0; r < 4; r++) {
            const float4 e = *reinterpret_cast<const float4*>(&se0[r * 64 + kc * 4]);
            X[r * 2]     = fmaf(e.x, a.x, fmaf(e.y, a.y, fmaf(e.z, a.z, fmaf(e.w, a.w, X[r * 2]))));
            X[r * 2 + 1] = fmaf(e.x, b.x, fmaf(e.y, b.y, fmaf(e.z, b.z, fmaf(e.w, b.w, X[r * 2 + 1]))));
        }
    }

    const float sbw = g_pre[65];
    const float c1s = g_pre[67];

    #pragma unroll
    for (int c = 0; c < 2; c++) {
        const int i1c = i1 + c;
        if (i1c > NE1) break;
        const float s1 = g_s1[i1c], q1 = g_q1[i1c], d1 = g_d1[i1c];
        const int   i1g = i1c >> 3;
        const float f1g = (float)(i1c & 7) * 0.125f;
        const float la = fmaf(f1g, sw0[i1g + 1] - sw0[i1g], sw0[i1g]);
        const float lb = fmaf(f1g, sw0[264 + i1g + 1] - sw0[264 + i1g], sw0[264 + i1g]);
        #pragma unroll
        for (int r = 0; r < 4; r++) {
            const int i0 = i0seg * 4 + r;
            const float w0 = fmaf((float)r * 0.25f, lb - la, la);
            const float w1 = 1.0f - w0;
            const float S = w0 * sS[r] + w1 * s1;
            const float Q = w0 * w0 * sS[4 + r] + 2.0f * w0 * w1 * X[r * 2 + c] + w1 * w1 * q1;
            const float D = w0 * sS[8 + r] + w1 * d1;
            const float mu   = S * (1.0f / 64.0f);
            const float var  = Q * (1.0f / 64.0f) - mu * mu;
            const float rstd = rsqrtf(var + 1e-5f);
            const float o    = fmaf((D - mu * c1s), rstd, sbw);
            if (i0 <= NE0) g_out2d[i0 * OST + i1c] = o;
        }
    }
}

// ==================== K4: main — one bilinear lookup per pixel =============
__global__ void __launch_bounds__(256)
gnab_main(const float* __restrict__ coords,
          const float* __restrict__ cost,
          float* __restrict__ out)
{
    const int row = blockIdx.x;        // b*256 + i
    const int j   = threadIdx.x;
    const int b   = row >> 8;
    const int i   = row & 255;
    const int pixel = row * 256 + j;

    const float x0 = __ldg(&cost[pixel]);
    const float2 ci = __ldg(reinterpret_cast<const float2*>(&coords[(b * 256 + i) * 2]));
    const float2 cj = __ldg(reinterpret_cast<const float2*>(&coords[(b * 256 + j) * 2]));
    const float dx = ci.x - cj.x;
    const float dy = ci.y - cj.y;

    // diamond pseudo-angle sigma in [0,4]
    const float ax = fabsf(dx), ay = fabsf(dy);
    const float den = ax + ay;
    const float t = (den > 0.0f) ? __fdividef(ay, den) : 0.0f;
    float tau;
    if (dx >= 0.0f) tau = (dy >= 0.0f) ? t : 4.0f - t;
    else            tau = (dy >= 0.0f) ? 2.0f - t : 2.0f + t;
    const float sigma = (tau > 2.0f) ? tau - 2.0f : tau + 2.0f;

    float u0 = x0 * (float)NE0;
    int i0 = (int)u0;
    i0 = (i0 < 0) ? 0 : ((i0 > NE0 - 1) ? NE0 - 1 : i0);
    const float f0 = u0 - (float)i0;

    float u1 = sigma * ((float)NE1 * 0.25f);
    int i1 = (int)u1;
    i1 = (i1 < 0) ? 0 : ((i1 > NE1 - 1) ? NE1 - 1 : i1);
    const float f1 = u1 - (float)i1;

    const float* R = &g_out2d[i0 * OST + i1];
    const float t00 = __ldg(R);
    const float t01 = __ldg(R + 1);
    const float t10 = __ldg(R + OST);
    const float t11 = __ldg(R + OST + 1);
    const float la = fmaf(f1, t01 - t00, t00);
    const float lb = fmaf(f1, t11 - t10, t10);
    out[pixel] = fmaf(f0, lb - la, la);
}

// ============================ launch =======================================
extern "C" void kernel_launch(void* const* d_in, const int* in_sizes, int n_in,
                              void* d_out, int out_size)
{
    const float* coords = (const float*)d_in[0];
    const float* cost   = (const float*)d_in[1];
    const float* lsc    = (const float*)d_in[2];
    const float* W1     = (const float*)d_in[3];
    const float* b1     = (const float*)d_in[4];
    const float* W2     = (const float*)d_in[5];
    const float* b2     = (const float*)d_in[6];
    const float* fg     = (const float*)d_in[7];
    const float* fb     = (const float*)d_in[8];
    const float* Wg1    = (const float*)d_in[9];
    const float* bg1    = (const float*)d_in[10];
    const float* Wg2    = (const float*)d_in[11];
    const float* bg2    = (const float*)d_in[12];
    const float* temp   = (const float*)d_in[13];
    const float* lng    = (const float*)d_in[14];
    const float* lnb    = (const float*)d_in[15];
    const float* Wo     = (const float*)d_in[16];
    const float* bo     = (const float*)d_in[17];
    float* out          = (float*)d_out;

    k_nodes<<<NB_TOT + 1, 64>>>(lsc, W1, b1, W2, b2, fg, fb,
                                Wg1, bg1, Wg2, bg2, temp, lng, lnb, Wo, bo);
    k_w2d<<<(129 * 257 + 255) / 256, 256>>>();
    k_out2d<<<129 * 5, 256>>>();
    gnab_main<<<2048, 256>>>(coords, cost, out);
}

// round 13
// speedup vs baseline: 1.7998x; 1.7998x over previous
#include <cuda_runtime.h>
#include <math.h>

// ---------------------------------------------------------------------------
// GatingNeuralAdaptiveBias — output-table form, coalesced builders.
//   out(x0, sigma) tabulated 257 x 1025 fp32 (1 MB, L2) -> main = 1 bilinear.
//   K1 k_nodes : e0 rows, E1 TRANSPOSED (k-major), [s,q,d] sidecars,
//                coarse gate g rows, consts.
//   K2 k_w2d   : coarse w0(x0,sigma) 129 x 257 (sigmoid applied).
//   K3 k_out2d : X = E0 @ E1^T (coalesced via e1t) + closed-form LN epilogue.
//   K4 main    : x0, sigma -> bilinear(out2d).
// ---------------------------------------------------------------------------

typedef unsigned int uint;

#define PI_F 3.14159265358979323846f
#define NE0 256
#define NE1 1024
#define NG0 128
#define NG1 256
#define OST 1025               // out2d row stride
#define E1TS 1056              // e1t row stride (padded)

__device__ __align__(16) float g_e0f[260 * 64];
__device__ __align__(16) float g_e1t[64 * E1TS];          // [k][i1]
__device__ __align__(16) float g_s0[260], g_q0[260], g_d0[260];
__device__ __align__(16) float g_s1[1032], g_q1[1032], g_d1[1032];
__device__ __align__(16) float g_g0c[132 * 64];
__device__ __align__(16) float g_g1c[260 * 64];
__device__ __align__(16) float g_w2d[129 * 257 + 8];
__device__ __align__(16) float g_out2d[257 * OST + 8];
// g_pre: [0..63] wd ; 64 itemp ; 65 sbw ; 66 bg2d ; 67 c1s
__device__ __align__(16) float g_pre[68];

__device__ __forceinline__ float silu_acc(float v) { return v / (1.0f + expf(-v)); }

// theta at a sigma node (build side); sigma in [0,4]; node 0 -> -pi.
__device__ __forceinline__ float theta_from_sigma(float sigma, int ent) {
    if (ent == 0) return -PI_F;
    const float tau = (sigma >= 2.0f) ? sigma - 2.0f : sigma + 2.0f;
    float x, y;
    if      (tau < 1.0f) { x = 1.0f - tau; y = tau; }
    else if (tau < 2.0f) { x = 1.0f - tau; y = 2.0f - tau; }
    else if (tau < 3.0f) { x = tau - 3.0f; y = 2.0f - tau; }
    else                 { x = tau - 3.0f; y = tau - 4.0f; }
    return atan2f(y, x);
}

// ==================== K1: node rows + sidecars + consts ====================
#define NB_E0 257
#define NB_E1 1025
#define NB_G0 129
#define NB_G1 257
#define NB_TOT (NB_E0 + NB_E1 + NB_G0 + NB_G1)   // 1668; grid = 1669
__global__ void __launch_bounds__(64)
k_nodes(const float* __restrict__ lsc,
        const float* __restrict__ W1,  const float* __restrict__ b1,
        const float* __restrict__ W2,  const float* __restrict__ b2,
        const float* __restrict__ fg,  const float* __restrict__ fb,
        const float* __restrict__ Wg1, const float* __restrict__ bg1,
        const float* __restrict__ Wg2, const float* __restrict__ bg2,
        const float* __restrict__ temp,
        const float* __restrict__ lng, const float* __restrict__ lnb,
        const float* __restrict__ Wo,  const float* __restrict__ bo)
{
    const int blk = blockIdx.x;
    const int tid = threadIdx.x;

    if (blk == NB_TOT) {                  // constants
        g_pre[tid] = Wg2[2 * tid] - Wg2[2 * tid + 1];
        if (tid == 0) {
            float s = bo[0], cs = 0.0f;
            for (int k = 0; k < 64; k++) { s += lnb[k] * Wo[k]; cs += lng[k] * Wo[k]; }
            g_pre[64] = expf(-temp[0]);
            g_pre[65] = s;
            g_pre[66] = bg2[0] - bg2[1];
            g_pre[67] = cs;
        }
        return;
    }

    __shared__ float sh[64];
    __shared__ float sred[6];

    int mode, ch, ent;
    if      (blk < NB_E0)                 { mode = 0; ch = 0; ent = blk; }
    else if (blk < NB_E0 + NB_E1)         { mode = 0; ch = 1; ent = blk - NB_E0; }
    else if (blk < NB_E0 + NB_E1 + NB_G0) { mode = 1; ch = 0; ent = blk - NB_E0 - NB_E1; }
    else                                  { mode = 1; ch = 1; ent = blk - NB_E0 - NB_E1 - NB_G0; }

    float x;
    if (ch == 0) x = (float)ent * (mode ? (1.0f / NG0) : (1.0f / NE0));
    else {
        const float sig = (float)ent * (mode ? (4.0f / NG1) : (4.0f / NE1));
        x = theta_from_sigma(sig, ent);
    }
    const float sc = expf(lsc[ch]);

    float ft[9];
    ft[0] = x * sc;
    #pragma unroll
    for (int q = 0; q < 4; q++) {
        float s, c;
        sincosf(x * (float)(1 << q), &s, &c);
        ft[1 + 2 * q] = s * sc;
        ft[2 + 2 * q] = c * sc;
    }

    float z = b1[tid];
    #pragma unroll
    for (int f = 0; f < 9; f++) z = fmaf(ft[f], W1[f * 64 + tid], z);
    sh[tid] = silu_acc(z);
    __syncthreads();

    float e = 0.0f;
    #pragma unroll 8
    for (int j = 0; j < 64; j++) e = fmaf(sh[j], W2[j * 64 + tid], e);
    e = fmaf(e + b2[tid], fg[ch * 64 + tid], fb[ch * 64 + tid]);

    if (mode == 0) {
        if (ch) g_e1t[tid * E1TS + ent] = e;       // TRANSPOSED store
        else    g_e0f[ent * 64 + tid]  = e;
        const float c1d = lng[tid] * Wo[tid];
        float s = e, q = e * e, d = e * c1d;
        #pragma unroll
        for (int o = 16; o > 0; o >>= 1) {
            s += __shfl_xor_sync(0xFFFFFFFFu, s, o);
            q += __shfl_xor_sync(0xFFFFFFFFu, q, o);
            d += __shfl_xor_sync(0xFFFFFFFFu, d, o);
        }
        if ((tid & 31) == 0) {
            const int w = tid >> 5;
            sred[w * 3 + 0] = s;  sred[w * 3 + 1] = q;  sred[w * 3 + 2] = d;
        }
        __syncthreads();
        if (tid == 0) {
            if (ch) { g_s1[ent] = sred[0] + sred[3]; g_q1[ent] = sred[1] + sred[4]; g_d1[ent] = sred[2] + sred[5]; }
            else    { g_s0[ent] = sred[0] + sred[3]; g_q0[ent] = sred[1] + sred[4]; g_d0[ent] = sred[2] + sred[5]; }
        }
    } else {
        __syncthreads();
        sh[tid] = e;
        __syncthreads();
        float g = (ch == 0) ? bg1[tid] : 0.0f;
        #pragma unroll 8
        for (int k = 0; k < 64; k++)
            g = fmaf(sh[k], Wg1[(ch * 64 + k) * 64 + tid], g);
        (ch ? g_g1c : g_g0c)[ent * 64 + tid] = g;
    }
}

// ==================== K2: coarse w0 table ==================================
__global__ void __launch_bounds__(256)
k_w2d()
{
    __shared__ float s_wd[64];
    const int tid = threadIdx.x;
    if (tid < 64) s_wd[tid] = g_pre[tid];
    __syncthreads();

    const int idx = blockIdx.x * 256 + tid;
    if (idx >= 129 * 257) return;
    const int i0 = idx / 257;
    const int i1 = idx - i0 * 257;

    const float4* a = reinterpret_cast<const float4*>(&g_g0c[i0 * 64]);
    const float4* b = reinterpret_cast<const float4*>(&g_g1c[i1 * 64]);
    float acc = g_pre[66];
    #pragma unroll 4
    for (int k = 0; k < 16; k++) {
        const float4 av = __ldg(&a[k]);
        const float4 bv = __ldg(&b[k]);
        acc = fmaf(silu_acc(av.x + bv.x), s_wd[4 * k],     acc);
        acc = fmaf(silu_acc(av.y + bv.y), s_wd[4 * k + 1], acc);
        acc = fmaf(silu_acc(av.z + bv.z), s_wd[4 * k + 2], acc);
        acc = fmaf(silu_acc(av.w + bv.w), s_wd[4 * k + 3], acc);
    }
    g_w2d[idx] = 1.0f / (1.0f + expf(-acc * g_pre[64]));
}

// ==================== K3: out2d build (coalesced cross-GEMM) ===============
// grid = 65 i0-groups (4 rows) x 5 i1-segments (256 cols); thread = 1 column.
__global__ void __launch_bounds__(256)
k_out2d()
{
    __shared__ __align__(16) float se0[4 * 64];
    __shared__ float sS[12];

    const int blk   = blockIdx.x;
    const int i0seg = blk / 5;
    const int i1seg = blk - i0seg * 5;
    const int tid   = threadIdx.x;

    {   // stage 4 e0 rows
        const int r = tid >> 6, k = tid & 63;
        const int i0 = i0seg * 4 + r;
        se0[tid] = (i0 <= NE0) ? g_e0f[i0 * 64 + k] : 0.0f;
    }
    if (tid < 4) {
        const int i0 = i0seg * 4 + tid;
        const int ic = (i0 <= NE0) ? i0 : NE0;
        sS[tid] = g_s0[ic];  sS[4 + tid] = g_q0[ic];  sS[8 + tid] = g_d0[ic];
    }
    __syncthreads();

    const int i1 = i1seg * 256 + tid;
    if (i1 > NE1) return;

    // X[r] = e0_r . e1_i1 (e1t reads coalesced: lanes = consecutive i1)
    float X[4] = {0, 0, 0, 0};
    #pragma unroll 8
    for (int k = 0; k < 64; k++) {
        const float a = __ldg(&g_e1t[k * E1TS + i1]);
        X[0] = fmaf(se0[k],       a, X[0]);
        X[1] = fmaf(se0[64 + k],  a, X[1]);
        X[2] = fmaf(se0[128 + k], a, X[2]);
        X[3] = fmaf(se0[192 + k], a, X[3]);
    }

    const float sbw = g_pre[65];
    const float c1s = g_pre[67];
    const float s1 = g_s1[i1], q1 = g_q1[i1], d1 = g_d1[i1];

    // w0 coarse coords in i1 (NE1/NG1 = 4)
    int   i1c = i1 >> 2;
    float f1c = (float)(i1 & 3) * 0.25f;
    if (i1c > NG1 - 1) { i1c = NG1 - 1; f1c = 1.0f; }

    #pragma unroll
    for (int r = 0; r < 4; r++) {
        const int i0 = i0seg * 4 + r;
        if (i0 > NE0) break;
        // w0 coarse coords in i0 (NE0/NG0 = 2)
        int   i0c = i0 >> 1;
        float f0c = (float)(i0 & 1) * 0.5f;
        if (i0c > NG0 - 1) { i0c = NG0 - 1; f0c = 1.0f; }

        const float* W = &g_w2d[i0c * 257 + i1c];
        const float t00 = __ldg(W),       t01 = __ldg(W + 1);
        const float t10 = __ldg(W + 257), t11 = __ldg(W + 258);
        const float la = fmaf(f1c, t01 - t00, t00);
        const float lb = fmaf(f1c, t11 - t10, t10);
        const float w0 = fmaf(f0c, lb - la, la);
        const float w1 = 1.0f - w0;

        const float S = w0 * sS[r] + w1 * s1;
        const float Q = w0 * w0 * sS[4 + r] + 2.0f * w0 * w1 * X[r] + w1 * w1 * q1;
        const float D = w0 * sS[8 + r] + w1 * d1;
        const float mu   = S * (1.0f / 64.0f);
        const float var  = Q * (1.0f / 64.0f) - mu * mu;
        const float rstd = rsqrtf(var + 1e-5f);
        g_out2d[i0 * OST + i1] = fmaf((D - mu * c1s), rstd, sbw);
    }
}

// ==================== K4: main — one bilinear lookup per pixel =============
__global__ void __launch_bounds__(256)
gnab_main(const float* __restrict__ coords,
          const float* __restrict__ cost,
          float* __restrict__ out)
{
    const int row = blockIdx.x;        // b*256 + i
    const int j   = threadIdx.x;
    const int b   = row >> 8;
    const int i   = row & 255;
    const int pixel = row * 256 + j;

    const float x0 = __ldg(&cost[pixel]);
    const float2 ci = __ldg(reinterpret_cast<const float2*>(&coords[(b * 256 + i) * 2]));
    const float2 cj = __ldg(reinterpret_cast<const float2*>(&coords[(b * 256 + j) * 2]));
    const float dx = ci.x - cj.x;
    const float dy = ci.y - cj.y;

    // diamond pseudo-angle sigma in [0,4]
    const float ax = fabsf(dx), ay = fabsf(dy);
    const float den = ax + ay;
    const float t = (den > 0.0f) ? __fdividef(ay, den) : 0.0f;
    float tau;
    if (dx >= 0.0f) tau = (dy >= 0.0f) ? t : 4.0f - t;
    else            tau = (dy >= 0.0f) ? 2.0f - t : 2.0f + t;
    const float sigma = (tau > 2.0f) ? tau - 2.0f : tau + 2.0f;

    float u0 = x0 * (float)NE0;
    int i0 = (int)u0;
    i0 = (i0 < 0) ? 0 : ((i0 > NE0 - 1) ? NE0 - 1 : i0);
    const float f0 = u0 - (float)i0;

    float u1 = sigma * ((float)NE1 * 0.25f);
    int i1 = (int)u1;
    i1 = (i1 < 0) ? 0 : ((i1 > NE1 - 1) ? NE1 - 1 : i1);
    const float f1 = u1 - (float)i1;

    const float* R = &g_out2d[i0 * OST + i1];
    const float t00 = __ldg(R);
    const float t01 = __ldg(R + 1);
    const float t10 = __ldg(R + OST);
    const float t11 = __ldg(R + OST + 1);
    const float la = fmaf(f1, t01 - t00, t00);
    const float lb = fmaf(f1, t11 - t10, t10);
    out[pixel] = fmaf(f0, lb - la, la);
}

// ============================ launch =======================================
extern "C" void kernel_launch(void* const* d_in, const int* in_sizes, int n_in,
                              void* d_out, int out_size)
{
    const float* coords = (const float*)d_in[0];
    const float* cost   = (const float*)d_in[1];
    const float* lsc    = (const float*)d_in[2];
    const float* W1     = (const float*)d_in[3];
    const float* b1     = (const float*)d_in[4];
    const float* W2     = (const float*)d_in[5];
    const float* b2     = (const float*)d_in[6];
    const float* fg     = (const float*)d_in[7];
    const float* fb     = (const float*)d_in[8];
    const float* Wg1    = (const float*)d_in[9];
    const float* bg1    = (const float*)d_in[10];
    const float* Wg2    = (const float*)d_in[11];
    const float* bg2    = (const float*)d_in[12];
    const float* temp   = (const float*)d_in[13];
    const float* lng    = (const float*)d_in[14];
    const float* lnb    = (const float*)d_in[15];
    const float* Wo     = (const float*)d_in[16];
    const float* bo     = (const float*)d_in[17];
    float* out          = (float*)d_out;

    k_nodes<<<NB_TOT + 1, 64>>>(lsc, W1, b1, W2, b2, fg, fb,
                                Wg1, bg1, Wg2, bg2, temp, lng, lnb, Wo, bo);
    k_w2d<<<(129 * 257 + 255) / 256, 256>>>();
    k_out2d<<<65 * 5, 256>>>();
    gnab_main<<<2048, 256>>>(coords, cost, out);
}